// round 1
// baseline (speedup 1.0000x reference)
#include <cuda_runtime.h>

// Problem constants (fixed by setup_inputs)
#define BB    16
#define CIN   64
#define COUT  64
#define HH    224
#define WW    224
#define PHH   32
#define PWW   32
#define PLANE   (HH * WW)        // 50176
#define PLANE4  (PLANE / 4)      // 12544
#define W4      (WW / 4)         // 56
#define TOTAL4  (BB * COUT * PLANE4)  // 12,845,056 float4s

// Conv tiling
#define CIN_T 16                 // cin chunk held in smem
#define CO_T  16                 // cout tile per CTA
#define OH_T  8                  // output rows per CTA
#define CONV_BLOCKS (BB * (COUT / CO_T) * (PHH / OH_T))  // 16*4*4 = 256
#define COPY_BLOCKS 896
#define NTHREADS 256

// smem: input tile [CIN_T][10][36] padded cols for bank safety, weights [CIN_T*9][CO_T]
#define SIN_STRIDE_R 36
#define SIN_STRIDE_C (10 * SIN_STRIDE_R)   // 360 per cin

__global__ __launch_bounds__(NTHREADS, 4)
void inc_conv_fused_kernel(const float* __restrict__ in,      // (B,Cin,H,W)
                           const float* __restrict__ wgt,     // (Cout,Cin,3,3)
                           const float* __restrict__ bias,    // (Cout)
                           const float* __restrict__ src_out, // (B,Cout,H,W) stale
                           const int*   __restrict__ locs,    // (B,2) [y,x]
                           float*       __restrict__ dst)     // (B,Cout,H,W)
{
    __shared__ float s_in[CIN_T * SIN_STRIDE_C];       // 5760 f = 23040 B
    __shared__ float s_w[CIN_T * 9 * CO_T];            // 2304 f =  9216 B

    const int tid = threadIdx.x;

    if (blockIdx.x < CONV_BLOCKS) {
        // ------------------- CONV ROLE -------------------
        const int conv_id = blockIdx.x;
        const int b       = conv_id >> 4;          // 16 blocks per batch
        const int rem     = conv_id & 15;
        const int co0     = (rem >> 2) * CO_T;     // cout tile base
        const int oh0     = (rem & 3) * OH_T;      // output-row tile base (within patch)

        const int y = locs[2 * b];                 // patch origin (output coords)
        const int x = locs[2 * b + 1];

        const int oh_l = tid >> 5;                 // 0..7 local output row
        const int ow   = tid & 31;                 // 0..31 local output col

        float acc[CO_T];
        #pragma unroll
        for (int c = 0; c < CO_T; ++c) acc[c] = 0.0f;

        // input window (unpadded coords): rows [y+oh0-1, y+oh0+8], cols [x-1, x+32]
        const int gr0 = y + oh0 - 1;
        const int gc0 = x - 1;

        for (int ci0 = 0; ci0 < CIN; ci0 += CIN_T) {
            // load input chunk: CIN_T x 10 x 34
            for (int t = tid; t < CIN_T * 10 * 34; t += NTHREADS) {
                const int ci = t / (10 * 34);
                const int r  = (t / 34) % 10;
                const int c  = t % 34;
                const int gr = gr0 + r;
                const int gc = gc0 + c;
                float v = 0.0f;
                if (gr >= 0 && gc >= 0)  // high side is provably in-bounds
                    v = in[((size_t)(b * CIN + ci0 + ci) * HH + gr) * WW + gc];
                s_in[ci * SIN_STRIDE_C + r * SIN_STRIDE_R + c] = v;
            }
            // load weights transposed: s_w[(ci*9+k)*CO_T + co]
            for (int t = tid; t < CO_T * CIN_T * 9; t += NTHREADS) {
                const int co = t / (CIN_T * 9);
                const int r2 = t % (CIN_T * 9);
                const int ci = r2 / 9;
                const int k  = r2 % 9;
                s_w[(ci * 9 + k) * CO_T + co] =
                    wgt[((co0 + co) * CIN + ci0 + ci) * 9 + k];
            }
            __syncthreads();

            #pragma unroll 4
            for (int ci = 0; ci < CIN_T; ++ci) {
                const float* ibase = &s_in[ci * SIN_STRIDE_C + oh_l * SIN_STRIDE_R + ow];
                #pragma unroll
                for (int kh = 0; kh < 3; ++kh) {
                    const float i0 = ibase[kh * SIN_STRIDE_R + 0];
                    const float i1 = ibase[kh * SIN_STRIDE_R + 1];
                    const float i2 = ibase[kh * SIN_STRIDE_R + 2];
                    #pragma unroll
                    for (int kw = 0; kw < 3; ++kw) {
                        const float iv = (kw == 0) ? i0 : ((kw == 1) ? i1 : i2);
                        const float4* wp =
                            (const float4*)&s_w[(ci * 9 + kh * 3 + kw) * CO_T];
                        const float4 w0 = wp[0], w1 = wp[1], w2 = wp[2], w3 = wp[3];
                        acc[0]  += iv * w0.x;  acc[1]  += iv * w0.y;
                        acc[2]  += iv * w0.z;  acc[3]  += iv * w0.w;
                        acc[4]  += iv * w1.x;  acc[5]  += iv * w1.y;
                        acc[6]  += iv * w1.z;  acc[7]  += iv * w1.w;
                        acc[8]  += iv * w2.x;  acc[9]  += iv * w2.y;
                        acc[10] += iv * w2.z;  acc[11] += iv * w2.w;
                        acc[12] += iv * w3.x;  acc[13] += iv * w3.y;
                        acc[14] += iv * w3.z;  acc[15] += iv * w3.w;
                    }
                }
            }
            __syncthreads();
        }

        // store patch outputs (+bias); conv owns these addresses exclusively
        const int oy = y + oh0 + oh_l;
        const int ox = x + ow;
        #pragma unroll
        for (int c = 0; c < CO_T; ++c) {
            dst[((size_t)(b * COUT + co0 + c) * HH + oy) * WW + ox] =
                acc[c] + bias[co0 + c];
        }
    } else {
        // ------------------- COPY ROLE -------------------
        // Copy stale out_tensor -> dst for everything OUTSIDE the patch regions.
        int* s_loc = (int*)s_w;  // reuse smem
        if (tid < 2 * BB) s_loc[tid] = locs[tid];
        __syncthreads();

        const float4* __restrict__ src4 = (const float4*)src_out;
        float4*       __restrict__ dst4 = (float4*)dst;

        const int copy_id = blockIdx.x - CONV_BLOCKS;
        const int stride  = COPY_BLOCKS * NTHREADS;

        for (int i = copy_id * NTHREADS + tid; i < TOTAL4; i += stride) {
            const int bc = i / PLANE4;          // b*64 + c
            const int p  = i - bc * PLANE4;
            const int h  = p / W4;
            const int w0 = (p - h * W4) * 4;
            const int b  = bc >> 6;

            const int py = s_loc[2 * b];
            const int px = s_loc[2 * b + 1];

            const float4 v = src4[i];
            const unsigned dh = (unsigned)(h - py);
            if (dh < PHH && (w0 + 3) >= px && w0 < (px + PWW)) {
                // float4 overlaps the patch: write only out-of-patch lanes
                float* d = (float*)&dst4[i];
                const float* sv = (const float*)&v;
                #pragma unroll
                for (int j = 0; j < 4; ++j) {
                    const unsigned dw = (unsigned)(w0 + j - px);
                    if (dw >= PWW) d[j] = sv[j];
                }
            } else {
                dst4[i] = v;
            }
        }
    }
}

extern "C" void kernel_launch(void* const* d_in, const int* in_sizes, int n_in,
                              void* d_out, int out_size) {
    const float* in_tensor  = (const float*)d_in[0];
    const float* weights    = (const float*)d_in[1];
    const float* biases     = (const float*)d_in[2];
    const float* out_stale  = (const float*)d_in[3];
    const int*   locs       = (const int*)d_in[4];
    float*       out        = (float*)d_out;

    inc_conv_fused_kernel<<<CONV_BLOCKS + COPY_BLOCKS, NTHREADS>>>(
        in_tensor, weights, biases, out_stale, locs, out);
}

// round 2
// speedup vs baseline: 1.1723x; 1.1723x over previous
#include <cuda_runtime.h>

// Problem constants (fixed by setup_inputs)
#define BB    16
#define CIN   64
#define COUT  64
#define HH    224
#define WW    224
#define PHH   32
#define PWW   32
#define PLANE   (HH * WW)        // 50176 floats per (b,c) plane
#define PLANE4  (PLANE / 4)      // 12544 float4s per plane
#define W4      (WW / 4)         // 56 float4s per row
#define CLEAN4  ((HH - PHH) * W4)   // 10752 float4s outside patch rows
#define PATCH4  (PHH * W4)          // 1792 float4s in patch rows

// Conv tiling
#define CIN_T 16
#define CO_T  16
#define OH_T  8
#define CONV_BLOCKS (BB * (COUT / CO_T) * (PHH / OH_T))  // 256
#define COPY_BLOCKS (BB * COUT)                          // 1024: one plane per CTA
#define NTHREADS 256

#define SIN_STRIDE_R 36
#define SIN_STRIDE_C (10 * SIN_STRIDE_R)

__global__ __launch_bounds__(NTHREADS, 4)
void inc_conv_fused_kernel(const float* __restrict__ in,      // (B,Cin,H,W)
                           const float* __restrict__ wgt,     // (Cout,Cin,3,3)
                           const float* __restrict__ bias,    // (Cout)
                           const float* __restrict__ src_out, // (B,Cout,H,W) stale
                           const int*   __restrict__ locs,    // (B,2) [y,x]
                           float*       __restrict__ dst)     // (B,Cout,H,W)
{
    const int tid = threadIdx.x;

    if (blockIdx.x >= CONV_BLOCKS) {
        // ------------------- COPY ROLE: one (b,c) plane per CTA -------------------
        const int plane = blockIdx.x - CONV_BLOCKS;       // b*64 + c
        const int b     = plane >> 6;
        const int py    = __ldg(&locs[2 * b]);
        const int px    = __ldg(&locs[2 * b + 1]);

        const float4* __restrict__ s4 = (const float4*)src_out + (size_t)plane * PLANE4;
        float4*       __restrict__ d4 = (float4*)dst          + (size_t)plane * PLANE4;

        const int split = py * W4;   // float4s before the patch rows

        // --- clean rows: 10752 float4s, branchless skip over the 1792 patch-row block
        int i = tid;
        #pragma unroll 1
        for (; i + 3 * NTHREADS < CLEAN4; i += 4 * NTHREADS) {
            const int i0 = i, i1 = i + NTHREADS, i2 = i + 2 * NTHREADS, i3 = i + 3 * NTHREADS;
            const int k0 = i0 < split ? i0 : i0 + PATCH4;
            const int k1 = i1 < split ? i1 : i1 + PATCH4;
            const int k2 = i2 < split ? i2 : i2 + PATCH4;
            const int k3 = i3 < split ? i3 : i3 + PATCH4;
            const float4 v0 = __ldcs(s4 + k0);
            const float4 v1 = __ldcs(s4 + k1);
            const float4 v2 = __ldcs(s4 + k2);
            const float4 v3 = __ldcs(s4 + k3);
            __stcs(d4 + k0, v0);
            __stcs(d4 + k1, v1);
            __stcs(d4 + k2, v2);
            __stcs(d4 + k3, v3);
        }
        for (; i < CLEAN4; i += NTHREADS) {
            const int k = i < split ? i : i + PATCH4;
            __stcs(d4 + k, __ldcs(s4 + k));
        }

        // --- patch rows: contiguous block [split, split+1792); mask patch columns
        #pragma unroll 1
        for (int t = tid; t < PATCH4; t += NTHREADS) {
            const int j  = t % W4;               // float4 column 0..55
            const int w0 = j * 4;
            const int k  = split + t;
            const bool overlap = (w0 + 3 >= px) && (w0 <= px + PWW - 1);
            if (!overlap) {
                __stcs(d4 + k, __ldcs(s4 + k));
            } else {
                const bool covered = (w0 >= px) && (w0 + 3 <= px + PWW - 1);
                if (!covered) {
                    // boundary float4: copy only out-of-patch lanes
                    const float4 v = __ldcs(s4 + k);
                    float* d = (float*)(d4 + k);
                    const float* sv = (const float*)&v;
                    #pragma unroll
                    for (int jj = 0; jj < 4; ++jj) {
                        const unsigned dw = (unsigned)(w0 + jj - px);
                        if (dw >= PWW) d[jj] = sv[jj];
                    }
                }
                // fully covered -> conv owns it, skip
            }
        }
        return;
    }

    // ------------------- CONV ROLE -------------------
    __shared__ float s_in[CIN_T * SIN_STRIDE_C];
    __shared__ float s_w[CIN_T * 9 * CO_T];

    const int conv_id = blockIdx.x;
    const int b       = conv_id >> 4;
    const int rem     = conv_id & 15;
    const int co0     = (rem >> 2) * CO_T;
    const int oh0     = (rem & 3) * OH_T;

    const int y = locs[2 * b];
    const int x = locs[2 * b + 1];

    const int oh_l = tid >> 5;
    const int ow   = tid & 31;

    float acc[CO_T];
    #pragma unroll
    for (int c = 0; c < CO_T; ++c) acc[c] = 0.0f;

    const int gr0 = y + oh0 - 1;
    const int gc0 = x - 1;

    for (int ci0 = 0; ci0 < CIN; ci0 += CIN_T) {
        for (int t = tid; t < CIN_T * 10 * 34; t += NTHREADS) {
            const int ci = t / (10 * 34);
            const int r  = (t / 34) % 10;
            const int c  = t % 34;
            const int gr = gr0 + r;
            const int gc = gc0 + c;
            float v = 0.0f;
            if (gr >= 0 && gc >= 0)
                v = in[((size_t)(b * CIN + ci0 + ci) * HH + gr) * WW + gc];
            s_in[ci * SIN_STRIDE_C + r * SIN_STRIDE_R + c] = v;
        }
        for (int t = tid; t < CO_T * CIN_T * 9; t += NTHREADS) {
            const int co = t / (CIN_T * 9);
            const int r2 = t % (CIN_T * 9);
            const int ci = r2 / 9;
            const int k  = r2 % 9;
            s_w[(ci * 9 + k) * CO_T + co] =
                wgt[((co0 + co) * CIN + ci0 + ci) * 9 + k];
        }
        __syncthreads();

        #pragma unroll 4
        for (int ci = 0; ci < CIN_T; ++ci) {
            const float* ibase = &s_in[ci * SIN_STRIDE_C + oh_l * SIN_STRIDE_R + ow];
            #pragma unroll
            for (int kh = 0; kh < 3; ++kh) {
                const float i0 = ibase[kh * SIN_STRIDE_R + 0];
                const float i1 = ibase[kh * SIN_STRIDE_R + 1];
                const float i2 = ibase[kh * SIN_STRIDE_R + 2];
                #pragma unroll
                for (int kw = 0; kw < 3; ++kw) {
                    const float iv = (kw == 0) ? i0 : ((kw == 1) ? i1 : i2);
                    const float4* wp =
                        (const float4*)&s_w[(ci * 9 + kh * 3 + kw) * CO_T];
                    const float4 w0 = wp[0], w1 = wp[1], w2 = wp[2], w3 = wp[3];
                    acc[0]  += iv * w0.x;  acc[1]  += iv * w0.y;
                    acc[2]  += iv * w0.z;  acc[3]  += iv * w0.w;
                    acc[4]  += iv * w1.x;  acc[5]  += iv * w1.y;
                    acc[6]  += iv * w1.z;  acc[7]  += iv * w1.w;
                    acc[8]  += iv * w2.x;  acc[9]  += iv * w2.y;
                    acc[10] += iv * w2.z;  acc[11] += iv * w2.w;
                    acc[12] += iv * w3.x;  acc[13] += iv * w3.y;
                    acc[14] += iv * w3.z;  acc[15] += iv * w3.w;
                }
            }
        }
        __syncthreads();
    }

    const int oy = y + oh0 + oh_l;
    const int ox = x + ow;
    #pragma unroll
    for (int c = 0; c < CO_T; ++c) {
        dst[((size_t)(b * COUT + co0 + c) * HH + oy) * WW + ox] =
            acc[c] + bias[co0 + c];
    }
}

extern "C" void kernel_launch(void* const* d_in, const int* in_sizes, int n_in,
                              void* d_out, int out_size) {
    const float* in_tensor  = (const float*)d_in[0];
    const float* weights    = (const float*)d_in[1];
    const float* biases     = (const float*)d_in[2];
    const float* out_stale  = (const float*)d_in[3];
    const int*   locs       = (const int*)d_in[4];
    float*       out        = (float*)d_out;

    inc_conv_fused_kernel<<<CONV_BLOCKS + COPY_BLOCKS, NTHREADS>>>(
        in_tensor, weights, biases, out_stale, locs, out);
}